// round 12
// baseline (speedup 1.0000x reference)
#include <cuda_runtime.h>
#include <cuda_fp16.h>

#define CANVAS 1024
#define NSH 64
#define TEXN 512
#define QDIM 513                 // tap-origin index range 0..512 (tex coord -1..511)
#define BW 129                   // morton blocks per row: ceil(513/4)
#define BH 257                   // morton block rows:     ceil(513/2)
#define QTE (BW * BH * 8)        // entries per table per texture
#define T_EPS 1e-4f

// Split quad storage: for tap-origin (yi, xi),
//   table A entry = { v00.rg, v00.ba, v01.rg, v01.ba }  (top row taps,    16B)
//   table B entry = { v10.rg, v10.ba, v11.rg, v11.ba }  (bottom row taps, 16B)
// Same index into both tables. 128B line = 8 origins (Morton 4 wide x 2 tall).
// Out-of-bounds taps stored as zero (matches reference zero-fill).
__device__ uint4 g_texA[4 * QTE];   // ~17 MB
__device__ uint4 g_texB[4 * QTE];   // ~17 MB

__device__ __forceinline__ int half_off(int qy, int qx) {
    return ((((qy >> 1) * BW + (qx >> 2)) << 3) | ((qy & 1) << 2) | (qx & 3));
}

// Per-shape transform/color record (compacted into smem per tile).
struct __align__(16) ShapeXfm {
    float tx, ty, m00, m01;
    float m10, m11, r, g;
    float b; int texoff; float pad0, pad1;
};

// ---------------------------------------------------------------------------
// Kernel 1: build the two fp16 half-tables (Morton 4x2 swizzled).
// ---------------------------------------------------------------------------
__global__ __launch_bounds__(256) void build_quad_kernel(const float* __restrict__ tex) {
    int t  = blockIdx.y;
    int qy = blockIdx.x;                   // 0..512
    int yi = qy - 1;                       // -1..511
    const int NPIX = TEXN * TEXN;
    const float* base = tex + (size_t)t * 4 * NPIX;
    uint4* tabA = g_texA + t * QTE;
    uint4* tabB = g_texB + t * QTE;

    for (int qx = threadIdx.x; qx < QDIM; qx += 256) {
        int xi = qx - 1;                   // -1..511

        float vals[4][4];  // [tap][chan]  taps: 00,01,10,11
        #pragma unroll
        for (int ty2 = 0; ty2 < 2; ty2++) {
            #pragma unroll
            for (int tx2 = 0; tx2 < 2; tx2++) {
                int y = yi + ty2, x = xi + tx2;
                bool ok = ((unsigned)x < (unsigned)TEXN) && ((unsigned)y < (unsigned)TEXN);
                int off = y * TEXN + x;
                #pragma unroll
                for (int ch = 0; ch < 4; ch++)
                    vals[ty2 * 2 + tx2][ch] = ok ? __ldg(base + ch * NPIX + off) : 0.0f;
            }
        }

        __half2 h[8];
        #pragma unroll
        for (int tap = 0; tap < 4; tap++) {
            h[tap * 2 + 0] = __floats2half2_rn(vals[tap][0], vals[tap][1]);
            h[tap * 2 + 1] = __floats2half2_rn(vals[tap][2], vals[tap][3]);
        }

        int o = half_off(qy, qx);
        tabA[o] = *reinterpret_cast<uint4*>(&h[0]);   // v00, v01
        tabB[o] = *reinterpret_cast<uint4*>(&h[4]);   // v10, v11
    }
}

// Bilerp from the two fetched half-entries -> (rg, ba) floats.
__device__ __forceinline__ void bilerp(uint4 qa, uint4 qb, float wx, float wy,
                                       float2& rgf, float2& baf)
{
    __half2 rg00 = *reinterpret_cast<const __half2*>(&qa.x);
    __half2 ba00 = *reinterpret_cast<const __half2*>(&qa.y);
    __half2 rg01 = *reinterpret_cast<const __half2*>(&qa.z);
    __half2 ba01 = *reinterpret_cast<const __half2*>(&qa.w);
    __half2 rg10 = *reinterpret_cast<const __half2*>(&qb.x);
    __half2 ba10 = *reinterpret_cast<const __half2*>(&qb.y);
    __half2 rg11 = *reinterpret_cast<const __half2*>(&qb.z);
    __half2 ba11 = *reinterpret_cast<const __half2*>(&qb.w);

    __half2 wx2 = __float2half2_rn(wx);
    __half2 wy2 = __float2half2_rn(wy);

    __half2 rg_t = __hfma2(wx2, __hsub2(rg01, rg00), rg00);
    __half2 ba_t = __hfma2(wx2, __hsub2(ba01, ba00), ba00);
    __half2 rg_b = __hfma2(wx2, __hsub2(rg11, rg10), rg10);
    __half2 ba_b = __hfma2(wx2, __hsub2(ba11, ba10), ba10);
    __half2 rg   = __hfma2(wy2, __hsub2(rg_b, rg_t), rg_t);
    __half2 ba   = __hfma2(wy2, __hsub2(ba_b, ba_t), ba_t);

    rgf = __half22float2(rg);
    baf = __half22float2(ba);
}

// ---------------------------------------------------------------------------
// Kernel 2: render. TWO pixels per thread (vertical pair); warp = 8x8 pixel
// block; block = 32x16 tile. Branchless dual-sample body: both samples'
// loads issued together (MLP=4), composite predicated by validity.
// ---------------------------------------------------------------------------
__global__ __launch_bounds__(256) void render_kernel(const int* __restrict__ st,
                                                     const float* __restrict__ params,
                                                     float* __restrict__ out) {
    __shared__ ShapeXfm sxf[NSH];     // compacted, order-preserving
    __shared__ float4   sbox[NSH];    // compacted bboxes (for warp-level cull)
    __shared__ int s_cnt0;
    __shared__ int s_nlive;

    int tid = threadIdx.x;            // 0..255 flat

    // tile bounds (pixel centers), tile = 32x16
    float tX0 = (float)(blockIdx.x * 32) + 0.5f;
    float tX1 = tX0 + 31.0f;
    float tY0 = (float)(blockIdx.y * 16) + 0.5f;
    float tY1 = tY0 + 15.0f;

    // --- per-tile shape prep + compaction (first 2 warps) ---
    bool pass = false;
    ShapeXfm xf;
    float4 bbox;
    if (tid < NSH) {
        const float* p = params + tid * 9;
        float tx = p[0] * (float)CANVAS;
        float ty = p[1] * (float)CANVAS;
        float W  = (float)CANVAS * (0.05f + 0.95f * p[2]);
        float H  = (float)CANVAS * (0.05f + 0.95f * p[3]);
        float as = p[4], ac = p[5];
        float nrm = sqrtf(as * as + ac * ac) + 1e-8f;
        float c = ac / nrm, s = as / nrm;
        float fx = (float)TEXN / W;
        float fy = (float)TEXN / H;

        xf.tx = tx; xf.ty = ty;
        xf.m00 =  c * fx;  xf.m01 = s * fx;
        xf.m10 = -s * fy;  xf.m11 = c * fy;
        xf.r = p[6]; xf.g = p[7]; xf.b = p[8];
        xf.texoff = st[tid] * QTE;
        xf.pad0 = xf.pad1 = 0.f;

        float uh = 0.5f * W * (1.0f + 2.0f / TEXN) + 2.0f;
        float vh = 0.5f * H * (1.0f + 2.0f / TEXN) + 2.0f;
        float ex = fabsf(c) * uh + fabsf(s) * vh;
        float ey = fabsf(s) * uh + fabsf(c) * vh;
        bbox = make_float4(tx - ex, tx + ex, ty - ey, ty + ey);
        pass = !(tX1 < bbox.x || tX0 > bbox.y || tY1 < bbox.z || tY0 > bbox.w);
    }

    unsigned mask = 0;
    int pos = 0;
    if (tid < NSH) {
        mask = __ballot_sync(0xffffffffu, pass);
        pos = __popc(mask & ((1u << (tid & 31)) - 1u));
        if (tid == 0) s_cnt0 = __popc(mask);
    }
    __syncthreads();
    if (tid < NSH) {
        int base = (tid < 32) ? 0 : s_cnt0;
        if (pass) { sxf[base + pos] = xf; sbox[base + pos] = bbox; }
        if (tid == 32) s_nlive = s_cnt0 + __popc(mask);
    }
    __syncthreads();

    int nlive = s_nlive;

    // warp -> 8x8 pixel block; thread -> vertical pixel pair
    int lane = tid & 31;
    int warp = tid >> 5;              // 0..7
    int lx = lane & 7;                // 0..7
    int lyt = lane >> 3;              // 0..3 -> rows 2*lyt, 2*lyt+1
    int bx0 = blockIdx.x * 32 + (warp & 3) * 8;
    int by0 = blockIdx.y * 16 + (warp >> 2) * 8;
    int x  = bx0 + lx;
    int y0 = by0 + lyt * 2;
    float px  = (float)x + 0.5f;
    float py0 = (float)y0 + 0.5f;

    // warp block bounds (pixel centers) — warp-uniform 8x8
    float wX0 = (float)bx0 + 0.5f, wX1 = wX0 + 7.0f;
    float wY0 = (float)by0 + 0.5f, wY1 = wY0 + 7.0f;

    // Reverse compositing per pixel: out = C + T * canvas0(=1)
    float Cr0 = 0.f, Cg0 = 0.f, Cb0 = 0.f, T0 = 1.f;
    float Cr1 = 0.f, Cg1 = 0.f, Cb1 = 0.f, T1 = 1.f;

    for (int k = nlive - 1; k >= 0; k--) {
        if (__all_sync(0xffffffffu, (T0 <= T_EPS) && (T1 <= T_EPS))) break;

        // warp-uniform 8x8 bbox cull
        float4 bb = sbox[k];
        if (wX1 < bb.x || wX0 > bb.y || wY1 < bb.z || wY0 > bb.w)
            continue;

        const ShapeXfm rec = sxf[k];
        float dx = px  - rec.tx;
        float dy = py0 - rec.ty;
        float fu0 = fmaf(rec.m00, dx, fmaf(rec.m01, dy, 256.5f));
        float fv0 = fmaf(rec.m10, dx, fmaf(rec.m11, dy, 256.5f));
        float fu1 = fu0 + rec.m01;     // +1 in canvas y
        float fv1 = fv0 + rec.m11;

        // indices + validity, branchless (clamped address is always safe;
        // invalid samples contribute exactly 0 via the Ta select below)
        int xi0 = __float2int_rd(fu0), yi0 = __float2int_rd(fv0);
        int xi1 = __float2int_rd(fu1), yi1 = __float2int_rd(fv1);
        bool v0 = ((unsigned)xi0 < (unsigned)QDIM) & ((unsigned)yi0 < (unsigned)QDIM);
        bool v1 = ((unsigned)xi1 < (unsigned)QDIM) & ((unsigned)yi1 < (unsigned)QDIM);
        int cx0 = min(max(xi0, 0), QDIM - 1), cy0 = min(max(yi0, 0), QDIM - 1);
        int cx1 = min(max(xi1, 0), QDIM - 1), cy1 = min(max(yi1, 0), QDIM - 1);
        int o0 = rec.texoff + half_off(cy0, cx0);
        int o1 = rec.texoff + half_off(cy1, cx1);

        // all 4 loads issued together -> overlapped latency
        uint4 qa0 = __ldg(g_texA + o0);
        uint4 qb0 = __ldg(g_texB + o0);
        uint4 qa1 = __ldg(g_texA + o1);
        uint4 qb1 = __ldg(g_texB + o1);

        float2 rgf0, baf0, rgf1, baf1;
        bilerp(qa0, qb0, fu0 - (float)xi0, fv0 - (float)yi0, rgf0, baf0);
        bilerp(qa1, qb1, fu1 - (float)xi1, fv1 - (float)yi1, rgf1, baf1);

        float Ta0 = v0 ? T0 * baf0.y : 0.0f;
        Cr0 = fmaf(Ta0, rgf0.x * rec.r, Cr0);
        Cg0 = fmaf(Ta0, rgf0.y * rec.g, Cg0);
        Cb0 = fmaf(Ta0, baf0.x * rec.b, Cb0);
        T0  = T0 - Ta0;

        float Ta1 = v1 ? T1 * baf1.y : 0.0f;
        Cr1 = fmaf(Ta1, rgf1.x * rec.r, Cr1);
        Cg1 = fmaf(Ta1, rgf1.y * rec.g, Cg1);
        Cb1 = fmaf(Ta1, baf1.x * rec.b, Cb1);
        T1  = T1 - Ta1;
    }

    int o = y0 * CANVAS + x;
    out[o] = Cr0 + T0;
    out[CANVAS * CANVAS + o] = Cg0 + T0;
    out[2 * CANVAS * CANVAS + o] = Cb0 + T0;
    o += CANVAS;
    out[o] = Cr1 + T1;
    out[CANVAS * CANVAS + o] = Cg1 + T1;
    out[2 * CANVAS * CANVAS + o] = Cb1 + T1;
}

// ---------------------------------------------------------------------------
extern "C" void kernel_launch(void* const* d_in, const int* in_sizes, int n_in,
                              void* d_out, int out_size) {
    const int*   shape_type = (const int*)d_in[0];
    const float* params     = (const float*)d_in[1];
    const float* textures   = (const float*)d_in[2];
    float* out = (float*)d_out;

    dim3 bgrid(QDIM, 4);
    build_quad_kernel<<<bgrid, 256>>>(textures);

    dim3 blk(256);
    dim3 grd(CANVAS / 32, CANVAS / 16);
    render_kernel<<<grd, blk>>>(shape_type, params, out);
}

// round 13
// speedup vs baseline: 1.4471x; 1.4471x over previous
#include <cuda_runtime.h>
#include <cuda_fp16.h>

#define CANVAS 1024
#define NSH 64
#define TEXN 512
#define QDIM 513                 // tap-origin index range 0..512 (tex coord -1..511)
#define BW 129                   // morton blocks per row: ceil(513/4)
#define BH 257                   // morton block rows:     ceil(513/2)
#define QTE (BW * BH * 8)        // entries per table per texture
#define T_EPS 1e-4f

// Split quad storage: for tap-origin (yi, xi),
//   table A entry = { v00.rg, v00.ba, v01.rg, v01.ba }  (top row taps,    16B)
//   table B entry = { v10.rg, v10.ba, v11.rg, v11.ba }  (bottom row taps, 16B)
// Same index into both tables. 128B line = 8 origins (Morton 4 wide x 2 tall).
// Out-of-bounds taps stored as zero (matches reference zero-fill).
__device__ uint4 g_texA[4 * QTE];   // ~17 MB
__device__ uint4 g_texB[4 * QTE];   // ~17 MB

__device__ __forceinline__ int half_off(int qy, int qx) {
    return ((((qy >> 1) * BW + (qx >> 2)) << 3) | ((qy & 1) << 2) | (qx & 3));
}

// Per-shape transform/color record (compacted into smem per tile).
struct __align__(16) ShapeXfm {
    float tx, ty, m00, m01;
    float m10, m11, r, g;
    float b; int texoff; float pad0, pad1;
};

// ---------------------------------------------------------------------------
// Kernel 1: build the two fp16 half-tables (Morton 4x2 swizzled).
// ---------------------------------------------------------------------------
__global__ __launch_bounds__(256) void build_quad_kernel(const float* __restrict__ tex) {
    int t  = blockIdx.y;
    int qy = blockIdx.x;                   // 0..512
    int yi = qy - 1;                       // -1..511
    const int NPIX = TEXN * TEXN;
    const float* base = tex + (size_t)t * 4 * NPIX;
    uint4* tabA = g_texA + t * QTE;
    uint4* tabB = g_texB + t * QTE;

    for (int qx = threadIdx.x; qx < QDIM; qx += 256) {
        int xi = qx - 1;                   // -1..511

        float vals[4][4];  // [tap][chan]  taps: 00,01,10,11
        #pragma unroll
        for (int ty2 = 0; ty2 < 2; ty2++) {
            #pragma unroll
            for (int tx2 = 0; tx2 < 2; tx2++) {
                int y = yi + ty2, x = xi + tx2;
                bool ok = ((unsigned)x < (unsigned)TEXN) && ((unsigned)y < (unsigned)TEXN);
                int off = y * TEXN + x;
                #pragma unroll
                for (int ch = 0; ch < 4; ch++)
                    vals[ty2 * 2 + tx2][ch] = ok ? __ldg(base + ch * NPIX + off) : 0.0f;
            }
        }

        __half2 h[8];
        #pragma unroll
        for (int tap = 0; tap < 4; tap++) {
            h[tap * 2 + 0] = __floats2half2_rn(vals[tap][0], vals[tap][1]);
            h[tap * 2 + 1] = __floats2half2_rn(vals[tap][2], vals[tap][3]);
        }

        int o = half_off(qy, qx);
        tabA[o] = *reinterpret_cast<uint4*>(&h[0]);   // v00, v01
        tabB[o] = *reinterpret_cast<uint4*>(&h[4]);   // v10, v11
    }
}

// Bilerp from the two fetched half-entries -> (rg, ba) floats.
__device__ __forceinline__ void bilerp(uint4 qa, uint4 qb, float wx, float wy,
                                       float2& rgf, float2& baf)
{
    __half2 rg00 = *reinterpret_cast<const __half2*>(&qa.x);
    __half2 ba00 = *reinterpret_cast<const __half2*>(&qa.y);
    __half2 rg01 = *reinterpret_cast<const __half2*>(&qa.z);
    __half2 ba01 = *reinterpret_cast<const __half2*>(&qa.w);
    __half2 rg10 = *reinterpret_cast<const __half2*>(&qb.x);
    __half2 ba10 = *reinterpret_cast<const __half2*>(&qb.y);
    __half2 rg11 = *reinterpret_cast<const __half2*>(&qb.z);
    __half2 ba11 = *reinterpret_cast<const __half2*>(&qb.w);

    __half2 wx2 = __float2half2_rn(wx);
    __half2 wy2 = __float2half2_rn(wy);

    __half2 rg_t = __hfma2(wx2, __hsub2(rg01, rg00), rg00);
    __half2 ba_t = __hfma2(wx2, __hsub2(ba01, ba00), ba00);
    __half2 rg_b = __hfma2(wx2, __hsub2(rg11, rg10), rg10);
    __half2 ba_b = __hfma2(wx2, __hsub2(ba11, ba10), ba10);
    __half2 rg   = __hfma2(wy2, __hsub2(rg_b, rg_t), rg_t);
    __half2 ba   = __hfma2(wy2, __hsub2(ba_b, ba_t), ba_t);

    rgf = __half22float2(rg);
    baf = __half22float2(ba);
}

// ---------------------------------------------------------------------------
// Kernel 2: render. TWO pixels per thread (vertical pair); warp = 8x8 pixel
// block; block = 32x16 tile. Per-lane activity branch preserved (wavefront
// filter), but inside the active path all 4 loads are issued back-to-back
// (MLP=4); a dead sample's load is redirected to the live sample's line.
// ---------------------------------------------------------------------------
__global__ __launch_bounds__(256) void render_kernel(const int* __restrict__ st,
                                                     const float* __restrict__ params,
                                                     float* __restrict__ out) {
    __shared__ ShapeXfm sxf[NSH];     // compacted, order-preserving
    __shared__ float4   sbox[NSH];    // compacted bboxes (for warp-level cull)
    __shared__ int s_cnt0;
    __shared__ int s_nlive;

    int tid = threadIdx.x;            // 0..255 flat

    // tile bounds (pixel centers), tile = 32x16
    float tX0 = (float)(blockIdx.x * 32) + 0.5f;
    float tX1 = tX0 + 31.0f;
    float tY0 = (float)(blockIdx.y * 16) + 0.5f;
    float tY1 = tY0 + 15.0f;

    // --- per-tile shape prep + compaction (first 2 warps) ---
    bool pass = false;
    ShapeXfm xf;
    float4 bbox;
    if (tid < NSH) {
        const float* p = params + tid * 9;
        float tx = p[0] * (float)CANVAS;
        float ty = p[1] * (float)CANVAS;
        float W  = (float)CANVAS * (0.05f + 0.95f * p[2]);
        float H  = (float)CANVAS * (0.05f + 0.95f * p[3]);
        float as = p[4], ac = p[5];
        float nrm = sqrtf(as * as + ac * ac) + 1e-8f;
        float c = ac / nrm, s = as / nrm;
        float fx = (float)TEXN / W;
        float fy = (float)TEXN / H;

        xf.tx = tx; xf.ty = ty;
        xf.m00 =  c * fx;  xf.m01 = s * fx;
        xf.m10 = -s * fy;  xf.m11 = c * fy;
        xf.r = p[6]; xf.g = p[7]; xf.b = p[8];
        xf.texoff = st[tid] * QTE;
        xf.pad0 = xf.pad1 = 0.f;

        float uh = 0.5f * W * (1.0f + 2.0f / TEXN) + 2.0f;
        float vh = 0.5f * H * (1.0f + 2.0f / TEXN) + 2.0f;
        float ex = fabsf(c) * uh + fabsf(s) * vh;
        float ey = fabsf(s) * uh + fabsf(c) * vh;
        bbox = make_float4(tx - ex, tx + ex, ty - ey, ty + ey);
        pass = !(tX1 < bbox.x || tX0 > bbox.y || tY1 < bbox.z || tY0 > bbox.w);
    }

    unsigned mask = 0;
    int pos = 0;
    if (tid < NSH) {
        mask = __ballot_sync(0xffffffffu, pass);
        pos = __popc(mask & ((1u << (tid & 31)) - 1u));
        if (tid == 0) s_cnt0 = __popc(mask);
    }
    __syncthreads();
    if (tid < NSH) {
        int base = (tid < 32) ? 0 : s_cnt0;
        if (pass) { sxf[base + pos] = xf; sbox[base + pos] = bbox; }
        if (tid == 32) s_nlive = s_cnt0 + __popc(mask);
    }
    __syncthreads();

    int nlive = s_nlive;

    // warp -> 8x8 pixel block; thread -> vertical pixel pair
    int lane = tid & 31;
    int warp = tid >> 5;              // 0..7
    int lx = lane & 7;                // 0..7
    int lyt = lane >> 3;              // 0..3 -> rows 2*lyt, 2*lyt+1
    int bx0 = blockIdx.x * 32 + (warp & 3) * 8;
    int by0 = blockIdx.y * 16 + (warp >> 2) * 8;
    int x  = bx0 + lx;
    int y0 = by0 + lyt * 2;
    float px  = (float)x + 0.5f;
    float py0 = (float)y0 + 0.5f;

    // warp block bounds (pixel centers) — warp-uniform 8x8
    float wX0 = (float)bx0 + 0.5f, wX1 = wX0 + 7.0f;
    float wY0 = (float)by0 + 0.5f, wY1 = wY0 + 7.0f;

    // Reverse compositing per pixel: out = C + T * canvas0(=1)
    float Cr0 = 0.f, Cg0 = 0.f, Cb0 = 0.f, T0 = 1.f;
    float Cr1 = 0.f, Cg1 = 0.f, Cb1 = 0.f, T1 = 1.f;

    for (int k = nlive - 1; k >= 0; k--) {
        if (__all_sync(0xffffffffu, (T0 <= T_EPS) && (T1 <= T_EPS))) break;

        // warp-uniform 8x8 bbox cull
        float4 bb = sbox[k];
        if (wX1 < bb.x || wX0 > bb.y || wY1 < bb.z || wY0 > bb.w)
            continue;

        const ShapeXfm rec = sxf[k];
        float dx = px  - rec.tx;
        float dy = py0 - rec.ty;
        float fu0 = fmaf(rec.m00, dx, fmaf(rec.m01, dy, 256.5f));
        float fv0 = fmaf(rec.m10, dx, fmaf(rec.m11, dy, 256.5f));
        float fu1 = fu0 + rec.m01;     // +1 in canvas y
        float fv1 = fv0 + rec.m11;

        int xi0 = __float2int_rd(fu0), yi0 = __float2int_rd(fv0);
        int xi1 = __float2int_rd(fu1), yi1 = __float2int_rd(fv1);
        bool v0 = ((unsigned)xi0 < (unsigned)QDIM) & ((unsigned)yi0 < (unsigned)QDIM);
        bool v1 = ((unsigned)xi1 < (unsigned)QDIM) & ((unsigned)yi1 < (unsigned)QDIM);
        bool a0 = v0 & (T0 > T_EPS);
        bool a1 = v1 & (T1 > T_EPS);

        // per-lane wavefront filter: skip when both samples dead
        if (!(a0 | a1)) continue;

        int o0 = rec.texoff + half_off(yi0, xi0);
        int o1 = rec.texoff + half_off(yi1, xi1);
        // dead sample loads the live sample's line -> no extra wavefront
        o0 = a0 ? o0 : o1;
        o1 = a1 ? o1 : o0;

        // all 4 loads issued together -> overlapped latency
        uint4 qa0 = __ldg(g_texA + o0);
        uint4 qb0 = __ldg(g_texB + o0);
        uint4 qa1 = __ldg(g_texA + o1);
        uint4 qb1 = __ldg(g_texB + o1);

        float2 rgf0, baf0, rgf1, baf1;
        bilerp(qa0, qb0, fu0 - (float)xi0, fv0 - (float)yi0, rgf0, baf0);
        bilerp(qa1, qb1, fu1 - (float)xi1, fv1 - (float)yi1, rgf1, baf1);

        float Ta0 = a0 ? T0 * baf0.y : 0.0f;
        Cr0 = fmaf(Ta0, rgf0.x * rec.r, Cr0);
        Cg0 = fmaf(Ta0, rgf0.y * rec.g, Cg0);
        Cb0 = fmaf(Ta0, baf0.x * rec.b, Cb0);
        T0  = T0 - Ta0;

        float Ta1 = a1 ? T1 * baf1.y : 0.0f;
        Cr1 = fmaf(Ta1, rgf1.x * rec.r, Cr1);
        Cg1 = fmaf(Ta1, rgf1.y * rec.g, Cg1);
        Cb1 = fmaf(Ta1, baf1.x * rec.b, Cb1);
        T1  = T1 - Ta1;
    }

    int o = y0 * CANVAS + x;
    out[o] = Cr0 + T0;
    out[CANVAS * CANVAS + o] = Cg0 + T0;
    out[2 * CANVAS * CANVAS + o] = Cb0 + T0;
    o += CANVAS;
    out[o] = Cr1 + T1;
    out[CANVAS * CANVAS + o] = Cg1 + T1;
    out[2 * CANVAS * CANVAS + o] = Cb1 + T1;
}

// ---------------------------------------------------------------------------
extern "C" void kernel_launch(void* const* d_in, const int* in_sizes, int n_in,
                              void* d_out, int out_size) {
    const int*   shape_type = (const int*)d_in[0];
    const float* params     = (const float*)d_in[1];
    const float* textures   = (const float*)d_in[2];
    float* out = (float*)d_out;

    dim3 bgrid(QDIM, 4);
    build_quad_kernel<<<bgrid, 256>>>(textures);

    dim3 blk(256);
    dim3 grd(CANVAS / 32, CANVAS / 16);
    render_kernel<<<grd, blk>>>(shape_type, params, out);
}

// round 14
// speedup vs baseline: 1.5706x; 1.0853x over previous
#include <cuda_runtime.h>
#include <cuda_fp16.h>

#define CANVAS 1024
#define NSH 64
#define TEXN 512
#define QDIM 513                 // tap-origin index range 0..512 (tex coord -1..511)
#define VXDIM 514                // x entries: 0..513 (second access reaches qx+1=513)
#define VBW 129                  // morton blocks per row: ceil(516/4)
#define VBH 257                  // morton block rows: ceil(514/2)
#define VTE (VBW * VBH * 8)      // entries per texture
#define T_EPS 1e-4f

// Column-pair table: V[qy][qx] = { texel(yi, xi), texel(yi+1, xi) } as fp16
// RGBA pairs {rgTop, baTop, rgBot, baBot}, where yi=qy-1, xi=qx-1.
// A bilinear sample at origin (xi,yi) reads V[qy][qx] (left column) and
// V[qy][qx+1] (right column) — same table, adjacent entries: with Morton 4x2
// blocking both usually hit the same 128B line. One 16B/origin table =>
// half the line footprint of the old split-A/B scheme. OOB texels are zero.
__device__ uint4 g_texV[4 * VTE];   // ~17 MB scratch

__device__ __forceinline__ int voff(int qy, int qx) {
    return ((((qy >> 1) * VBW + (qx >> 2)) << 3) | ((qy & 1) << 2) | (qx & 3));
}

// Per-shape transform/color record (compacted into smem per tile).
struct __align__(16) ShapeXfm {
    float tx, ty, m00, m01;
    float m10, m11, r, g;
    float b; int texoff; float pad0, pad1;
};

// ---------------------------------------------------------------------------
// Kernel 1: build the column-pair fp16 table (Morton 4x2 swizzled).
// grid: (513 qy-rows, 4 tex), block 256 sweeps qx 0..513.
// ---------------------------------------------------------------------------
__global__ __launch_bounds__(256) void build_tex_kernel(const float* __restrict__ tex) {
    int t  = blockIdx.y;
    int qy = blockIdx.x;                   // 0..512
    int yi = qy - 1;                       // -1..511
    const int NPIX = TEXN * TEXN;
    const float* base = tex + (size_t)t * 4 * NPIX;
    uint4* tab = g_texV + t * VTE;

    bool topok_y = (unsigned)yi < (unsigned)TEXN;
    bool botok_y = (unsigned)(yi + 1) < (unsigned)TEXN;

    for (int qx = threadIdx.x; qx < VXDIM; qx += 256) {
        int xi = qx - 1;                   // -1..512
        bool xok = (unsigned)xi < (unsigned)TEXN;

        float top[4] = {0.f, 0.f, 0.f, 0.f};
        float bot[4] = {0.f, 0.f, 0.f, 0.f};
        if (xok) {
            if (topok_y) {
                int off = yi * TEXN + xi;
                #pragma unroll
                for (int ch = 0; ch < 4; ch++) top[ch] = __ldg(base + ch * NPIX + off);
            }
            if (botok_y) {
                int off = (yi + 1) * TEXN + xi;
                #pragma unroll
                for (int ch = 0; ch < 4; ch++) bot[ch] = __ldg(base + ch * NPIX + off);
            }
        }

        __half2 h[4];
        h[0] = __floats2half2_rn(top[0], top[1]);   // rg top
        h[1] = __floats2half2_rn(top[2], top[3]);   // ba top
        h[2] = __floats2half2_rn(bot[0], bot[1]);   // rg bot
        h[3] = __floats2half2_rn(bot[2], bot[3]);   // ba bot

        tab[voff(qy, qx)] = *reinterpret_cast<uint4*>(&h[0]);
    }
}

// One bilinear sample + composite step. No-op if lane saturated or outside.
__device__ __forceinline__ void sample_composite(
    int texoff, float cr, float cg, float cb,
    float fu, float fv,
    float& Cr, float& Cg, float& Cb, float& T)
{
    if (T <= T_EPS) return;
    int qx = __float2int_rd(fu);    // valid 0..512
    int qy = __float2int_rd(fv);
    if (((unsigned)qx >= (unsigned)QDIM) || ((unsigned)qy >= (unsigned)QDIM))
        return;

    float wx = fu - (float)qx;
    float wy = fv - (float)qy;

    uint4 eL = __ldg(g_texV + texoff + voff(qy, qx));        // left column pair
    uint4 eR = __ldg(g_texV + texoff + voff(qy, qx + 1));    // right column pair

    __half2 rgTL = *reinterpret_cast<const __half2*>(&eL.x);
    __half2 baTL = *reinterpret_cast<const __half2*>(&eL.y);
    __half2 rgBL = *reinterpret_cast<const __half2*>(&eL.z);
    __half2 baBL = *reinterpret_cast<const __half2*>(&eL.w);
    __half2 rgTR = *reinterpret_cast<const __half2*>(&eR.x);
    __half2 baTR = *reinterpret_cast<const __half2*>(&eR.y);
    __half2 rgBR = *reinterpret_cast<const __half2*>(&eR.z);
    __half2 baBR = *reinterpret_cast<const __half2*>(&eR.w);

    __half2 wx2 = __float2half2_rn(wx);
    __half2 wy2 = __float2half2_rn(wy);

    // lerp within each column in y, then across columns in x
    __half2 rgL = __hfma2(wy2, __hsub2(rgBL, rgTL), rgTL);
    __half2 baL = __hfma2(wy2, __hsub2(baBL, baTL), baTL);
    __half2 rgR = __hfma2(wy2, __hsub2(rgBR, rgTR), rgTR);
    __half2 baR = __hfma2(wy2, __hsub2(baBR, baTR), baTR);
    __half2 rg  = __hfma2(wx2, __hsub2(rgR, rgL), rgL);
    __half2 ba  = __hfma2(wx2, __hsub2(baR, baL), baL);

    float2 rgf = __half22float2(rg);
    float2 baf = __half22float2(ba);

    float Ta = T * baf.y;           // T * alpha
    Cr = fmaf(Ta, rgf.x * cr, Cr);
    Cg = fmaf(Ta, rgf.y * cg, Cg);
    Cb = fmaf(Ta, baf.x * cb, Cb);
    T  = T - Ta;                    // T *= (1 - a)
}

// ---------------------------------------------------------------------------
// Kernel 2: render. TWO pixels per thread (vertical pair); warp = 8x8 pixel
// block; block = 32x16 tile. Per-tile shape compaction + per-warp bbox cull,
// reverse compositing with transmittance early-exit, fp16 bilerp.
// ---------------------------------------------------------------------------
__global__ __launch_bounds__(256) void render_kernel(const int* __restrict__ st,
                                                     const float* __restrict__ params,
                                                     float* __restrict__ out) {
    __shared__ ShapeXfm sxf[NSH];     // compacted, order-preserving
    __shared__ float4   sbox[NSH];    // compacted bboxes (for warp-level cull)
    __shared__ int s_cnt0;
    __shared__ int s_nlive;

    int tid = threadIdx.x;            // 0..255 flat

    // tile bounds (pixel centers), tile = 32x16
    float tX0 = (float)(blockIdx.x * 32) + 0.5f;
    float tX1 = tX0 + 31.0f;
    float tY0 = (float)(blockIdx.y * 16) + 0.5f;
    float tY1 = tY0 + 15.0f;

    // --- per-tile shape prep + compaction (first 2 warps) ---
    bool pass = false;
    ShapeXfm xf;
    float4 bbox;
    if (tid < NSH) {
        const float* p = params + tid * 9;
        float tx = p[0] * (float)CANVAS;
        float ty = p[1] * (float)CANVAS;
        float W  = (float)CANVAS * (0.05f + 0.95f * p[2]);
        float H  = (float)CANVAS * (0.05f + 0.95f * p[3]);
        float as = p[4], ac = p[5];
        float nrm = sqrtf(as * as + ac * ac) + 1e-8f;
        float c = ac / nrm, s = as / nrm;
        float fx = (float)TEXN / W;
        float fy = (float)TEXN / H;

        xf.tx = tx; xf.ty = ty;
        xf.m00 =  c * fx;  xf.m01 = s * fx;
        xf.m10 = -s * fy;  xf.m11 = c * fy;
        xf.r = p[6]; xf.g = p[7]; xf.b = p[8];
        xf.texoff = st[tid] * VTE;
        xf.pad0 = xf.pad1 = 0.f;

        float uh = 0.5f * W * (1.0f + 2.0f / TEXN) + 2.0f;
        float vh = 0.5f * H * (1.0f + 2.0f / TEXN) + 2.0f;
        float ex = fabsf(c) * uh + fabsf(s) * vh;
        float ey = fabsf(s) * uh + fabsf(c) * vh;
        bbox = make_float4(tx - ex, tx + ex, ty - ey, ty + ey);
        pass = !(tX1 < bbox.x || tX0 > bbox.y || tY1 < bbox.z || tY0 > bbox.w);
    }

    unsigned mask = 0;
    int pos = 0;
    if (tid < NSH) {
        mask = __ballot_sync(0xffffffffu, pass);
        pos = __popc(mask & ((1u << (tid & 31)) - 1u));
        if (tid == 0) s_cnt0 = __popc(mask);
    }
    __syncthreads();
    if (tid < NSH) {
        int base = (tid < 32) ? 0 : s_cnt0;
        if (pass) { sxf[base + pos] = xf; sbox[base + pos] = bbox; }
        if (tid == 32) s_nlive = s_cnt0 + __popc(mask);
    }
    __syncthreads();

    int nlive = s_nlive;

    // warp -> 8x8 pixel block; thread -> vertical pixel pair
    int lane = tid & 31;
    int warp = tid >> 5;              // 0..7
    int lx = lane & 7;                // 0..7
    int lyt = lane >> 3;              // 0..3 -> rows 2*lyt, 2*lyt+1
    int bx0 = blockIdx.x * 32 + (warp & 3) * 8;
    int by0 = blockIdx.y * 16 + (warp >> 2) * 8;
    int x  = bx0 + lx;
    int y0 = by0 + lyt * 2;
    float px  = (float)x + 0.5f;
    float py0 = (float)y0 + 0.5f;

    // warp block bounds (pixel centers) — warp-uniform 8x8
    float wX0 = (float)bx0 + 0.5f, wX1 = wX0 + 7.0f;
    float wY0 = (float)by0 + 0.5f, wY1 = wY0 + 7.0f;

    // Reverse compositing per pixel: out = C + T * canvas0(=1)
    float Cr0 = 0.f, Cg0 = 0.f, Cb0 = 0.f, T0 = 1.f;
    float Cr1 = 0.f, Cg1 = 0.f, Cb1 = 0.f, T1 = 1.f;

    for (int k = nlive - 1; k >= 0; k--) {
        if (__all_sync(0xffffffffu, (T0 <= T_EPS) && (T1 <= T_EPS))) break;

        // warp-uniform 8x8 bbox cull
        float4 bb = sbox[k];
        if (wX1 < bb.x || wX0 > bb.y || wY1 < bb.z || wY0 > bb.w)
            continue;

        const ShapeXfm rec = sxf[k];
        float dx = px  - rec.tx;
        float dy = py0 - rec.ty;
        float fu0 = fmaf(rec.m00, dx, fmaf(rec.m01, dy, 256.5f));
        float fv0 = fmaf(rec.m10, dx, fmaf(rec.m11, dy, 256.5f));
        float fu1 = fu0 + rec.m01;     // +1 in canvas y
        float fv1 = fv0 + rec.m11;

        sample_composite(rec.texoff, rec.r, rec.g, rec.b, fu0, fv0, Cr0, Cg0, Cb0, T0);
        sample_composite(rec.texoff, rec.r, rec.g, rec.b, fu1, fv1, Cr1, Cg1, Cb1, T1);
    }

    int o = y0 * CANVAS + x;
    out[o] = Cr0 + T0;
    out[CANVAS * CANVAS + o] = Cg0 + T0;
    out[2 * CANVAS * CANVAS + o] = Cb0 + T0;
    o += CANVAS;
    out[o] = Cr1 + T1;
    out[CANVAS * CANVAS + o] = Cg1 + T1;
    out[2 * CANVAS * CANVAS + o] = Cb1 + T1;
}

// ---------------------------------------------------------------------------
extern "C" void kernel_launch(void* const* d_in, const int* in_sizes, int n_in,
                              void* d_out, int out_size) {
    const int*   shape_type = (const int*)d_in[0];
    const float* params     = (const float*)d_in[1];
    const float* textures   = (const float*)d_in[2];
    float* out = (float*)d_out;

    dim3 bgrid(QDIM, 4);
    build_tex_kernel<<<bgrid, 256>>>(textures);

    dim3 blk(256);
    dim3 grd(CANVAS / 32, CANVAS / 16);
    render_kernel<<<grd, blk>>>(shape_type, params, out);
}